// round 15
// baseline (speedup 1.0000x reference)
#include <cuda_runtime.h>
#include <cuda_bf16.h>
#include <cstdint>

#define N_NODES 100000
#define N_EDGES 1200000
#define D 64
#define CAP 64                 // max in-degree capacity (Poisson(12): P(>=64) ~ 5e-26)
#define GEMM_NODES 32          // nodes per block; exact tiling
#define FPAD 68                // padded f row
#define EPAIRS (N_EDGES / 2)   // 600000 edge pairs
#define EBLOCKS ((EPAIRS + 255) / 256)   // 2344

// ---- scratch (__device__ globals, allocation-free) ----
__device__ int    g_count[N_NODES];
__device__ int2   g_edge[(size_t)N_NODES * CAP];   // {src, __float_as_int(norm[src])}
__device__ float  g_f1[(size_t)N_NODES * D];       // aggregated f1
__device__ float  g_f2[(size_t)N_NODES * D];       // aggregated f2
__device__ float2 g_Wh[2][8][8][32];   // [part][kstep][ntile][lane] hi frags
__device__ float2 g_Wl[2][8][8][32];   // lo residual frags

// ---- tf32 helpers ----
__device__ __forceinline__ uint32_t tf32_of(float a) {
    uint32_t r; asm("cvt.rna.tf32.f32 %0, %1;" : "=r"(r) : "f"(a));
    return r;
}
__device__ __forceinline__ void mma_tf32(float4& d,
    uint32_t a0, uint32_t a1, uint32_t a2, uint32_t a3,
    uint32_t b0, uint32_t b1)
{
    asm("mma.sync.aligned.m16n8k8.row.col.f32.tf32.tf32.f32 "
        "{%0,%1,%2,%3}, {%4,%5,%6,%7}, {%8,%9}, {%0,%1,%2,%3};"
        : "+f"(d.x), "+f"(d.y), "+f"(d.z), "+f"(d.w)
        : "r"(a0), "r"(a1), "r"(a2), "r"(a3), "r"(b0), "r"(b1));
}

// ---------------------------------------------------------------------------
// Build: blocks [0, EBLOCKS) scatter 2 edges/thread; tail 16 blocks
// precompute the hi/lo tf32 W fragments.
// ---------------------------------------------------------------------------
__global__ void __launch_bounds__(256) build_kernel(
    const int2* __restrict__ src2, const int2* __restrict__ dst2,
    const float* __restrict__ norm,
    const float* __restrict__ W1, const float* __restrict__ W2)
{
    int b = blockIdx.x;
    if (b < EBLOCKS) {
        int i = b * 256 + threadIdx.x;
        if (i >= EPAIRS) return;
        int2 s = __ldg(src2 + i);
        int2 d = __ldg(dst2 + i);
        float ns0 = __ldg(norm + s.x);
        float ns1 = __ldg(norm + s.y);
        int p0 = atomicAdd(&g_count[d.x], 1);
        int p1 = atomicAdd(&g_count[d.y], 1);
        g_edge[(size_t)d.x * CAP + p0] = make_int2(s.x, __float_as_int(ns0));
        g_edge[(size_t)d.y * CAP + p1] = make_int2(s.y, __float_as_int(ns1));
    } else {
        int idx = (b - EBLOCKS) * 256 + threadIdx.x;   // 0..4095
        if (idx >= 4096) return;
        int lane  = idx & 31;
        int ntile = (idx >> 5) & 7;
        int kstep = (idx >> 8) & 7;
        int part  = idx >> 11;
        const float* W = part ? W2 : W1;
        int g = lane >> 2, tig = lane & 3;
        int n  = ntile * 8 + g;
        int k0 = kstep * 8 + tig;
        float b0 = __ldg(W + k0 * D + n);
        float b1 = __ldg(W + (k0 + 4) * D + n);
        uint32_t h0 = tf32_of(b0), h1 = tf32_of(b1);
        float r0 = b0 - __uint_as_float(h0);
        float r1 = b1 - __uint_as_float(h1);
        g_Wh[part][kstep][ntile][lane] =
            make_float2(__uint_as_float(h0), __uint_as_float(h1));
        g_Wl[part][kstep][ntile][lane] =
            make_float2(__uint_as_float(tf32_of(r0)), __uint_as_float(tf32_of(r1)));
    }
}

// ---- one edge's contribution: a1 += c * v ----
__device__ __forceinline__ void edge_fma(float4 va, float c, float4& a1)
{
    a1.x = fmaf(va.x, c, a1.x); a1.y = fmaf(va.y, c, a1.y);
    a1.z = fmaf(va.z, c, a1.z); a1.w = fmaf(va.w, c, a1.w);
}

// ---------------------------------------------------------------------------
// Aggregation kernel (high occupancy): warp-per-node, 8 nodes/block.
// S = sum norm[s]*x[src]; f1 = norm[n]*S; f2 = x[n] (.) f1 -> global.
// ---------------------------------------------------------------------------
__global__ void __launch_bounds__(256, 6) agg_kernel(
    const float* __restrict__ x, const float* __restrict__ norm)
{
    int t = threadIdx.x;
    int w = t >> 5, lane = t & 31;
    int half = lane >> 4;
    int le = lane & 15;
    int n = blockIdx.x * 8 + w;          // 12500 * 8 = 100000 exact

    const float4* x4 = reinterpret_cast<const float4*>(x);
    int cnt = __ldg(g_count + n);
    const int2* ep = g_edge + (size_t)n * CAP;

    float4 a1 = make_float4(0.f, 0.f, 0.f, 0.f);
    int e = half;
    for (; e + 6 < cnt; e += 8) {
        int2 r0 = __ldg(ep + e);
        int2 r1 = __ldg(ep + e + 2);
        int2 r2 = __ldg(ep + e + 4);
        int2 r3 = __ldg(ep + e + 6);
        float4 v0 = __ldg(x4 + r0.x * 16 + le);
        float4 v1 = __ldg(x4 + r1.x * 16 + le);
        float4 v2 = __ldg(x4 + r2.x * 16 + le);
        float4 v3 = __ldg(x4 + r3.x * 16 + le);
        edge_fma(v0, __int_as_float(r0.y), a1);
        edge_fma(v1, __int_as_float(r1.y), a1);
        edge_fma(v2, __int_as_float(r2.y), a1);
        edge_fma(v3, __int_as_float(r3.y), a1);
    }
    for (; e + 2 < cnt; e += 4) {
        int2 r0 = __ldg(ep + e);
        int2 r1 = __ldg(ep + e + 2);
        float4 v0 = __ldg(x4 + r0.x * 16 + le);
        float4 v1 = __ldg(x4 + r1.x * 16 + le);
        edge_fma(v0, __int_as_float(r0.y), a1);
        edge_fma(v1, __int_as_float(r1.y), a1);
    }
    if (e < cnt) {
        int2 r0 = __ldg(ep + e);
        float4 v0 = __ldg(x4 + r0.x * 16 + le);
        edge_fma(v0, __int_as_float(r0.y), a1);
    }

    a1.x += __shfl_down_sync(0xffffffffu, a1.x, 16);
    a1.y += __shfl_down_sync(0xffffffffu, a1.y, 16);
    a1.z += __shfl_down_sync(0xffffffffu, a1.z, 16);
    a1.w += __shfl_down_sync(0xffffffffu, a1.w, 16);
    if (half == 0) {
        float nv = __ldg(norm + n);
        float4 vd = __ldg(x4 + n * 16 + le);
        float4 f1 = make_float4(a1.x * nv, a1.y * nv, a1.z * nv, a1.w * nv);
        float4 f2 = make_float4(f1.x * vd.x, f1.y * vd.y,
                                f1.z * vd.z, f1.w * vd.w);
        reinterpret_cast<float4*>(g_f1)[n * 16 + le] = f1;
        reinterpret_cast<float4*>(g_f2)[n * 16 + le] = f2;
    }
}

// ---------------------------------------------------------------------------
// GEMM kernel: stage f tiles global->smem, then 3xTF32 m16n8k8 warp MMA.
// 128 threads, 32 nodes/block; warp w owns cols [w*16, w*16+16).
// ---------------------------------------------------------------------------
__global__ void __launch_bounds__(128, 8) gemm_kernel(
    const float* __restrict__ b1v, const float* __restrict__ b2v,
    float* __restrict__ out)
{
    extern __shared__ float sh[];
    float* f1s = sh;                        // 32*68
    float* f2s = f1s + GEMM_NODES * FPAD;   // 32*68

    int t = threadIdx.x;
    int node0 = blockIdx.x * GEMM_NODES;
    int w = t >> 5, lane = t & 31;

    // ---- stage f tiles (coalesced float4 loads) ----
    const float4* f1g = reinterpret_cast<const float4*>(g_f1);
    const float4* f2g = reinterpret_cast<const float4*>(g_f2);
    #pragma unroll
    for (int i = 0; i < 4; i++) {
        int fi = i * 128 + t;          // 0..511 float4s = 32 rows x 16
        int row = fi >> 4;
        int q = fi & 15;
        float4 v1 = __ldg(f1g + node0 * 16 + fi);
        float4 v2 = __ldg(f2g + node0 * 16 + fi);
        *reinterpret_cast<float4*>(&f1s[row * FPAD + q * 4]) = v1;
        *reinterpret_cast<float4*>(&f2s[row * FPAD + q * 4]) = v2;
    }
    __syncthreads();

    // ---- 3xTF32 warp MMA ----
    int g = lane >> 2, tig = lane & 3;

    float4 acc[2][2];
    #pragma unroll
    for (int mt = 0; mt < 2; mt++)
        #pragma unroll
        for (int nt = 0; nt < 2; nt++)
            acc[mt][nt] = make_float4(0.f, 0.f, 0.f, 0.f);

    #pragma unroll
    for (int part = 0; part < 2; part++) {
        const float* fs = part ? f2s : f1s;
        #pragma unroll 2
        for (int ks = 0; ks < 8; ks++) {
            uint32_t bh[2][2], bl[2][2];
            #pragma unroll
            for (int nt = 0; nt < 2; nt++) {
                float2 h = __ldg(&g_Wh[part][ks][w * 2 + nt][lane]);
                float2 l = __ldg(&g_Wl[part][ks][w * 2 + nt][lane]);
                bh[nt][0] = __float_as_uint(h.x);
                bh[nt][1] = __float_as_uint(h.y);
                bl[nt][0] = __float_as_uint(l.x);
                bl[nt][1] = __float_as_uint(l.y);
            }
            #pragma unroll
            for (int mt = 0; mt < 2; mt++) {
                int r0 = mt * 16 + g;
                int c0 = ks * 8 + tig;
                float a0f = fs[r0 * FPAD + c0];
                float a1f = fs[(r0 + 8) * FPAD + c0];
                float a2f = fs[r0 * FPAD + c0 + 4];
                float a3f = fs[(r0 + 8) * FPAD + c0 + 4];
                uint32_t ah0 = tf32_of(a0f), ah1 = tf32_of(a1f);
                uint32_t ah2 = tf32_of(a2f), ah3 = tf32_of(a3f);
                uint32_t al0 = tf32_of(a0f - __uint_as_float(ah0));
                uint32_t al1 = tf32_of(a1f - __uint_as_float(ah1));
                uint32_t al2 = tf32_of(a2f - __uint_as_float(ah2));
                uint32_t al3 = tf32_of(a3f - __uint_as_float(ah3));
                #pragma unroll
                for (int nt = 0; nt < 2; nt++) {
                    mma_tf32(acc[mt][nt], ah0, ah1, ah2, ah3, bh[nt][0], bh[nt][1]);
                    mma_tf32(acc[mt][nt], ah0, ah1, ah2, ah3, bl[nt][0], bl[nt][1]);
                    mma_tf32(acc[mt][nt], al0, al1, al2, al3, bh[nt][0], bh[nt][1]);
                }
            }
        }
    }

    // ---- epilogue ----
    #pragma unroll
    for (int nt = 0; nt < 2; nt++) {
        int colb = w * 16 + nt * 8 + 2 * tig;
        float bx = __ldg(b1v + colb)     + __ldg(b2v + colb);
        float by = __ldg(b1v + colb + 1) + __ldg(b2v + colb + 1);
        #pragma unroll
        for (int mt = 0; mt < 2; mt++) {
            int row0 = node0 + mt * 16 + g;
            float2 lo = make_float2(acc[mt][nt].x + bx, acc[mt][nt].y + by);
            float2 hi = make_float2(acc[mt][nt].z + bx, acc[mt][nt].w + by);
            *reinterpret_cast<float2*>(&out[row0 * D + colb]) = lo;
            *reinterpret_cast<float2*>(&out[(row0 + 8) * D + colb]) = hi;
        }
    }
}

// ---------------------------------------------------------------------------
// Launch
// ---------------------------------------------------------------------------
extern "C" void kernel_launch(void* const* d_in, const int* in_sizes, int n_in,
                              void* d_out, int out_size)
{
    const float* x    = (const float*)d_in[0];
    const float* norm = (const float*)d_in[1];
    const int*   src  = (const int*)  d_in[2];
    const int*   dst  = (const int*)  d_in[3];
    const float* W1   = (const float*)d_in[4];
    const float* b1   = (const float*)d_in[5];
    const float* W2   = (const float*)d_in[6];
    const float* b2   = (const float*)d_in[7];
    float* out = (float*)d_out;

    void* count_ptr;
    cudaGetSymbolAddress(&count_ptr, g_count);
    cudaMemsetAsync(count_ptr, 0, sizeof(int) * N_NODES);

    build_kernel<<<EBLOCKS + 16, 256>>>(
        reinterpret_cast<const int2*>(src),
        reinterpret_cast<const int2*>(dst), norm, W1, W2);

    agg_kernel<<<N_NODES / 8, 256>>>(x, norm);   // 12500 blocks

    size_t shmem = sizeof(float) * (2 * GEMM_NODES * FPAD);
    cudaFuncSetAttribute(gemm_kernel,
                         cudaFuncAttributeMaxDynamicSharedMemorySize,
                         (int)shmem);
    gemm_kernel<<<N_NODES / GEMM_NODES, 128, shmem>>>(b1, b2, out);
}

// round 16
// speedup vs baseline: 1.2381x; 1.2381x over previous
#include <cuda_runtime.h>
#include <cuda_bf16.h>
#include <cstdint>

#define N_NODES 100000
#define N_EDGES 1200000
#define D 64
#define CAP 64                 // max in-degree capacity (Poisson(12): P(>=64) ~ 5e-26)
#define GEMM_NODES 32          // nodes per block; exact tiling
#define FPAD 68                // padded f row
#define EPAIRS (N_EDGES / 2)   // 600000 edge pairs
#define EBLOCKS ((EPAIRS + 255) / 256)   // 2344

// ---- scratch (__device__ globals, allocation-free) ----
__device__ int    g_count[N_NODES];
__device__ int2   g_edge[(size_t)N_NODES * CAP];   // {src, __float_as_int(norm[src])}
__device__ uint2  g_Wh[2][4][8][32];   // [part][k16step][ntile][lane] = {b0,b1} bf16x2 hi
__device__ uint2  g_Wl[2][4][8][32];   // lo residual frags

// ---- bf16 helpers ----
// pack two floats into bf16x2: upper half = hi_f, lower half = lo_f
__device__ __forceinline__ uint32_t bf2_pack(float upper_f, float lower_f) {
    uint32_t r;
    asm("cvt.rn.bf16x2.f32 %0, %1, %2;" : "=r"(r) : "f"(upper_f), "f"(lower_f));
    return r;
}
// exact bf16->f32 of the two halves (bit shifts)
__device__ __forceinline__ float bf2_lo_f(uint32_t u) {
    return __uint_as_float(u << 16);
}
__device__ __forceinline__ float bf2_hi_f(uint32_t u) {
    return __uint_as_float(u & 0xffff0000u);
}

__device__ __forceinline__ void mma_bf16(float4& d,
    uint32_t a0, uint32_t a1, uint32_t a2, uint32_t a3,
    uint32_t b0, uint32_t b1)
{
    asm("mma.sync.aligned.m16n8k16.row.col.f32.bf16.bf16.f32 "
        "{%0,%1,%2,%3}, {%4,%5,%6,%7}, {%8,%9}, {%0,%1,%2,%3};"
        : "+f"(d.x), "+f"(d.y), "+f"(d.z), "+f"(d.w)
        : "r"(a0), "r"(a1), "r"(a2), "r"(a3), "r"(b0), "r"(b1));
}

// convert a float2 (consecutive-k pair) into bf16x2 hi and lo frags
__device__ __forceinline__ void split_bf2(float2 p, uint32_t& hi, uint32_t& lo)
{
    hi = bf2_pack(p.y, p.x);
    float rx = p.x - bf2_lo_f(hi);
    float ry = p.y - bf2_hi_f(hi);
    lo = bf2_pack(ry, rx);
}

// ---------------------------------------------------------------------------
// Build: blocks [0, EBLOCKS) scatter 2 edges/thread; tail 8 blocks
// precompute the hi/lo bf16 W fragments (m16n8k16 B layout).
// B-frag (k16 x n8, col-major n): b0 = {W[k0+2t][n], W[k0+2t+1][n]},
// b1 = {W[k0+2t+8][n], W[k0+2t+9][n]}, t = lane&3, n = ntile*8 + lane>>2.
// ---------------------------------------------------------------------------
__global__ void __launch_bounds__(256) build_kernel(
    const int2* __restrict__ src2, const int2* __restrict__ dst2,
    const float* __restrict__ norm,
    const float* __restrict__ W1, const float* __restrict__ W2)
{
    int b = blockIdx.x;
    if (b < EBLOCKS) {
        int i = b * 256 + threadIdx.x;
        if (i >= EPAIRS) return;
        int2 s = __ldg(src2 + i);
        int2 d = __ldg(dst2 + i);
        float ns0 = __ldg(norm + s.x);
        float ns1 = __ldg(norm + s.y);
        int p0 = atomicAdd(&g_count[d.x], 1);
        int p1 = atomicAdd(&g_count[d.y], 1);
        g_edge[(size_t)d.x * CAP + p0] = make_int2(s.x, __float_as_int(ns0));
        g_edge[(size_t)d.y * CAP + p1] = make_int2(s.y, __float_as_int(ns1));
    } else {
        int idx = (b - EBLOCKS) * 256 + threadIdx.x;   // 0..2047
        if (idx >= 2048) return;
        int lane  = idx & 31;
        int ntile = (idx >> 5) & 7;
        int ks    = (idx >> 8) & 3;
        int part  = idx >> 10;
        const float* W = part ? W2 : W1;
        int g = lane >> 2, tig = lane & 3;
        int n  = ntile * 8 + g;
        int k0 = ks * 16 + 2 * tig;
        float2 pb0 = make_float2(__ldg(W + k0 * D + n),
                                 __ldg(W + (k0 + 1) * D + n));
        float2 pb1 = make_float2(__ldg(W + (k0 + 8) * D + n),
                                 __ldg(W + (k0 + 9) * D + n));
        uint32_t h0, l0, h1, l1;
        split_bf2(pb0, h0, l0);
        split_bf2(pb1, h1, l1);
        g_Wh[part][ks][ntile][lane] = make_uint2(h0, h1);
        g_Wl[part][ks][ntile][lane] = make_uint2(l0, l1);
    }
}

// ---- one edge's contribution: a1 += c * v ----
__device__ __forceinline__ void edge_fma(float4 va, float c, float4& a1)
{
    a1.x = fmaf(va.x, c, a1.x); a1.y = fmaf(va.y, c, a1.y);
    a1.z = fmaf(va.z, c, a1.z); a1.w = fmaf(va.w, c, a1.w);
}

// ---------------------------------------------------------------------------
// Fused aggregate + dual-GEMM. 128 threads, 32 nodes/block, 8 blocks/SM.
// Phase B: S = sum norm[s]*x[src]; f1 = norm[n]*S; f2 = x[n] (.) f1.
// Phase C: 3xBF16 m16n8k16 warp MMA (hi*hi + hi*lo + lo*hi split).
//          Warp w owns cols [w*16, w*16+16).
// ---------------------------------------------------------------------------
__global__ void __launch_bounds__(128, 8) fused_kernel(
    const float* __restrict__ x, const float* __restrict__ norm,
    const float* __restrict__ b1v, const float* __restrict__ b2v,
    float* __restrict__ out)
{
    extern __shared__ float sh[];
    float* f1s = sh;                        // 32*68
    float* f2s = f1s + GEMM_NODES * FPAD;   // 32*68

    int t = threadIdx.x;
    int node0 = blockIdx.x * GEMM_NODES;
    int w = t >> 5, lane = t & 31;

    // ---- Phase B ----
    int half = lane >> 4;
    int le = lane & 15;
    const float4* x4 = reinterpret_cast<const float4*>(x);

    int cnts[8];
    #pragma unroll
    for (int j = 0; j < 8; j++)
        cnts[j] = __ldg(g_count + node0 + w * 8 + j);

    #pragma unroll 1
    for (int j = 0; j < 8; j++) {
        int row = w * 8 + j;
        int n = node0 + row;
        int cnt = cnts[j];
        const int2* ep = g_edge + (size_t)n * CAP;

        float4 a1 = make_float4(0.f, 0.f, 0.f, 0.f);
        int e = half;
        for (; e + 6 < cnt; e += 8) {
            int2 r0 = __ldg(ep + e);
            int2 r1 = __ldg(ep + e + 2);
            int2 r2 = __ldg(ep + e + 4);
            int2 r3 = __ldg(ep + e + 6);
            float4 v0 = __ldg(x4 + r0.x * 16 + le);
            float4 v1 = __ldg(x4 + r1.x * 16 + le);
            float4 v2 = __ldg(x4 + r2.x * 16 + le);
            float4 v3 = __ldg(x4 + r3.x * 16 + le);
            edge_fma(v0, __int_as_float(r0.y), a1);
            edge_fma(v1, __int_as_float(r1.y), a1);
            edge_fma(v2, __int_as_float(r2.y), a1);
            edge_fma(v3, __int_as_float(r3.y), a1);
        }
        for (; e + 2 < cnt; e += 4) {
            int2 r0 = __ldg(ep + e);
            int2 r1 = __ldg(ep + e + 2);
            float4 v0 = __ldg(x4 + r0.x * 16 + le);
            float4 v1 = __ldg(x4 + r1.x * 16 + le);
            edge_fma(v0, __int_as_float(r0.y), a1);
            edge_fma(v1, __int_as_float(r1.y), a1);
        }
        if (e < cnt) {
            int2 r0 = __ldg(ep + e);
            float4 v0 = __ldg(x4 + r0.x * 16 + le);
            edge_fma(v0, __int_as_float(r0.y), a1);
        }

        a1.x += __shfl_down_sync(0xffffffffu, a1.x, 16);
        a1.y += __shfl_down_sync(0xffffffffu, a1.y, 16);
        a1.z += __shfl_down_sync(0xffffffffu, a1.z, 16);
        a1.w += __shfl_down_sync(0xffffffffu, a1.w, 16);
        if (half == 0) {
            float nv = __ldg(norm + n);
            float4 vd = __ldg(x4 + n * 16 + le);
            float4 f1 = make_float4(a1.x * nv, a1.y * nv,
                                    a1.z * nv, a1.w * nv);
            float4 f2 = make_float4(f1.x * vd.x, f1.y * vd.y,
                                    f1.z * vd.z, f1.w * vd.w);
            *reinterpret_cast<float4*>(&f1s[row * FPAD + 4 * le]) = f1;
            *reinterpret_cast<float4*>(&f2s[row * FPAD + 4 * le]) = f2;
        }
    }
    __syncthreads();

    // ---- Phase C: 3xBF16 m16n8k16 warp MMA ----
    int g = lane >> 2, tig = lane & 3;

    float4 acc[2][2];
    #pragma unroll
    for (int mt = 0; mt < 2; mt++)
        #pragma unroll
        for (int nt = 0; nt < 2; nt++)
            acc[mt][nt] = make_float4(0.f, 0.f, 0.f, 0.f);

    #pragma unroll
    for (int part = 0; part < 2; part++) {
        const float* fs = part ? f2s : f1s;
        #pragma unroll
        for (int ks = 0; ks < 4; ks++) {
            uint2 bh[2], bl[2];
            #pragma unroll
            for (int nt = 0; nt < 2; nt++) {
                bh[nt] = __ldg(&g_Wh[part][ks][w * 2 + nt][lane]);
                bl[nt] = __ldg(&g_Wl[part][ks][w * 2 + nt][lane]);
            }
            #pragma unroll
            for (int mt = 0; mt < 2; mt++) {
                int r0 = mt * 16 + g;
                int c0 = ks * 16 + 2 * tig;
                // A frag (row-major m16 x k16):
                // a0={A[g][c0],A[g][c0+1]} a1={A[g+8][c0],...}
                // a2={A[g][c0+8],A[g][c0+9]} a3={A[g+8][c0+8],...}
                float2 p0 = *reinterpret_cast<const float2*>(&fs[r0 * FPAD + c0]);
                float2 p1 = *reinterpret_cast<const float2*>(&fs[(r0 + 8) * FPAD + c0]);
                float2 p2 = *reinterpret_cast<const float2*>(&fs[r0 * FPAD + c0 + 8]);
                float2 p3 = *reinterpret_cast<const float2*>(&fs[(r0 + 8) * FPAD + c0 + 8]);
                uint32_t ah0, al0, ah1, al1, ah2, al2, ah3, al3;
                split_bf2(p0, ah0, al0);
                split_bf2(p1, ah1, al1);
                split_bf2(p2, ah2, al2);
                split_bf2(p3, ah3, al3);
                #pragma unroll
                for (int nt = 0; nt < 2; nt++) {
                    mma_bf16(acc[mt][nt], ah0, ah1, ah2, ah3, bh[nt].x, bh[nt].y);
                    mma_bf16(acc[mt][nt], ah0, ah1, ah2, ah3, bl[nt].x, bl[nt].y);
                    mma_bf16(acc[mt][nt], al0, al1, al2, al3, bh[nt].x, bh[nt].y);
                }
            }
        }
    }

    // ---- epilogue (C frag: c0=(g,2tig) c1=(g,2tig+1) c2/c3 = rows +8) ----
    #pragma unroll
    for (int nt = 0; nt < 2; nt++) {
        int colb = w * 16 + nt * 8 + 2 * tig;
        float bx = __ldg(b1v + colb)     + __ldg(b2v + colb);
        float by = __ldg(b1v + colb + 1) + __ldg(b2v + colb + 1);
        #pragma unroll
        for (int mt = 0; mt < 2; mt++) {
            int row0 = node0 + mt * 16 + g;
            float2 lo = make_float2(acc[mt][nt].x + bx, acc[mt][nt].y + by);
            float2 hi = make_float2(acc[mt][nt].z + bx, acc[mt][nt].w + by);
            *reinterpret_cast<float2*>(&out[row0 * D + colb]) = lo;
            *reinterpret_cast<float2*>(&out[(row0 + 8) * D + colb]) = hi;
        }
    }
}

// ---------------------------------------------------------------------------
// Launch
// ---------------------------------------------------------------------------
extern "C" void kernel_launch(void* const* d_in, const int* in_sizes, int n_in,
                              void* d_out, int out_size)
{
    const float* x    = (const float*)d_in[0];
    const float* norm = (const float*)d_in[1];
    const int*   src  = (const int*)  d_in[2];
    const int*   dst  = (const int*)  d_in[3];
    const float* W1   = (const float*)d_in[4];
    const float* b1   = (const float*)d_in[5];
    const float* W2   = (const float*)d_in[6];
    const float* b2   = (const float*)d_in[7];
    float* out = (float*)d_out;

    void* count_ptr;
    cudaGetSymbolAddress(&count_ptr, g_count);
    cudaMemsetAsync(count_ptr, 0, sizeof(int) * N_NODES);

    build_kernel<<<EBLOCKS + 8, 256>>>(
        reinterpret_cast<const int2*>(src),
        reinterpret_cast<const int2*>(dst), norm, W1, W2);

    size_t shmem = sizeof(float) * (2 * GEMM_NODES * FPAD);
    cudaFuncSetAttribute(fused_kernel,
                         cudaFuncAttributeMaxDynamicSharedMemorySize,
                         (int)shmem);
    fused_kernel<<<N_NODES / GEMM_NODES, 128, shmem>>>(x, norm, b1, b2, out);
}

// round 17
// speedup vs baseline: 1.3832x; 1.1172x over previous
#include <cuda_runtime.h>
#include <cuda_bf16.h>
#include <cstdint>

#define N_NODES 100000
#define N_EDGES 1200000
#define D 64
#define CAP 64                 // max in-degree capacity (Poisson(12): P(>=64) ~ 5e-26)
#define GEMM_NODES 32          // nodes per block; exact tiling
#define FPAD 68                // padded f row
#define EPAIRS (N_EDGES / 2)   // 600000 edge pairs
#define EBLOCKS ((EPAIRS + 255) / 256)   // 2344

// ---- scratch (__device__ globals, allocation-free) ----
__device__ int    g_count[N_NODES];
__device__ int2   g_edge[(size_t)N_NODES * CAP];   // {src, __float_as_int(norm[src])}
__device__ uint2  g_Wh[2][4][8][32];   // [part][k16step][ntile][lane] = {b0,b1} bf16x2 hi
__device__ uint2  g_Wl[2][4][8][32];   // lo residual frags

// ---- bf16 helpers ----
__device__ __forceinline__ uint32_t bf2_pack(float upper_f, float lower_f) {
    uint32_t r;
    asm("cvt.rn.bf16x2.f32 %0, %1, %2;" : "=r"(r) : "f"(upper_f), "f"(lower_f));
    return r;
}
__device__ __forceinline__ float bf2_lo_f(uint32_t u) {
    return __uint_as_float(u << 16);
}
__device__ __forceinline__ float bf2_hi_f(uint32_t u) {
    return __uint_as_float(u & 0xffff0000u);
}

__device__ __forceinline__ void mma_bf16(float4& d,
    uint32_t a0, uint32_t a1, uint32_t a2, uint32_t a3,
    uint32_t b0, uint32_t b1)
{
    asm("mma.sync.aligned.m16n8k16.row.col.f32.bf16.bf16.f32 "
        "{%0,%1,%2,%3}, {%4,%5,%6,%7}, {%8,%9}, {%0,%1,%2,%3};"
        : "+f"(d.x), "+f"(d.y), "+f"(d.z), "+f"(d.w)
        : "r"(a0), "r"(a1), "r"(a2), "r"(a3), "r"(b0), "r"(b1));
}

__device__ __forceinline__ void split_bf2(float2 p, uint32_t& hi, uint32_t& lo)
{
    hi = bf2_pack(p.y, p.x);
    float rx = p.x - bf2_lo_f(hi);
    float ry = p.y - bf2_hi_f(hi);
    lo = bf2_pack(ry, rx);
}

// ---------------------------------------------------------------------------
// Build: blocks [0, EBLOCKS) scatter 2 edges/thread; tail 8 blocks
// precompute the hi/lo bf16 W fragments (m16n8k16 B layout).
// ---------------------------------------------------------------------------
__global__ void __launch_bounds__(256) build_kernel(
    const int2* __restrict__ src2, const int2* __restrict__ dst2,
    const float* __restrict__ norm,
    const float* __restrict__ W1, const float* __restrict__ W2)
{
    int b = blockIdx.x;
    if (b < EBLOCKS) {
        int i = b * 256 + threadIdx.x;
        if (i >= EPAIRS) return;
        int2 s = __ldg(src2 + i);
        int2 d = __ldg(dst2 + i);
        float ns0 = __ldg(norm + s.x);
        float ns1 = __ldg(norm + s.y);
        int p0 = atomicAdd(&g_count[d.x], 1);
        int p1 = atomicAdd(&g_count[d.y], 1);
        g_edge[(size_t)d.x * CAP + p0] = make_int2(s.x, __float_as_int(ns0));
        g_edge[(size_t)d.y * CAP + p1] = make_int2(s.y, __float_as_int(ns1));
    } else {
        int idx = (b - EBLOCKS) * 256 + threadIdx.x;   // 0..2047
        if (idx >= 2048) return;
        int lane  = idx & 31;
        int ntile = (idx >> 5) & 7;
        int ks    = (idx >> 8) & 3;
        int part  = idx >> 10;
        const float* W = part ? W2 : W1;
        int g = lane >> 2, tig = lane & 3;
        int n  = ntile * 8 + g;
        int k0 = ks * 16 + 2 * tig;
        float2 pb0 = make_float2(__ldg(W + k0 * D + n),
                                 __ldg(W + (k0 + 1) * D + n));
        float2 pb1 = make_float2(__ldg(W + (k0 + 8) * D + n),
                                 __ldg(W + (k0 + 9) * D + n));
        uint32_t h0, l0, h1, l1;
        split_bf2(pb0, h0, l0);
        split_bf2(pb1, h1, l1);
        g_Wh[part][ks][ntile][lane] = make_uint2(h0, h1);
        g_Wl[part][ks][ntile][lane] = make_uint2(l0, l1);
    }
}

// ---- one edge's contribution: a1 += c * v ----
__device__ __forceinline__ void edge_fma(float4 va, float c, float4& a1)
{
    a1.x = fmaf(va.x, c, a1.x); a1.y = fmaf(va.y, c, a1.y);
    a1.z = fmaf(va.z, c, a1.z); a1.w = fmaf(va.w, c, a1.w);
}

// ---------------------------------------------------------------------------
// Fused aggregate + dual-GEMM. 128 threads, 32 nodes/block, 8 blocks/SM.
// Phase B: HALF-WARP-PER-NODE. Each 16-lane group owns a full 64-col row
//          (float4 lanes) and walks its node's edge list with int4 record
//          loads (2 records each) and a 4/2/1 ladder. The two halves of a
//          warp run independent nodes -> 2x concurrent entry chains, no
//          shfl-combine. 8 half-warps x 4 nodes = 32 nodes.
// Phase C: 3xBF16 m16n8k16 warp MMA (hi*hi + hi*lo + lo*hi).
// ---------------------------------------------------------------------------
__global__ void __launch_bounds__(128, 8) fused_kernel(
    const float* __restrict__ x, const float* __restrict__ norm,
    const float* __restrict__ b1v, const float* __restrict__ b2v,
    float* __restrict__ out)
{
    extern __shared__ float sh[];
    float* f1s = sh;                        // 32*68
    float* f2s = f1s + GEMM_NODES * FPAD;   // 32*68

    int t = threadIdx.x;
    int node0 = blockIdx.x * GEMM_NODES;
    int w = t >> 5, lane = t & 31;

    // ---- Phase B: half-warp-per-node ----
    int hw = t >> 4;              // 0..7 half-warp id
    int le = t & 15;              // float4 chunk within 64-col row
    const float4* x4 = reinterpret_cast<const float4*>(x);

    int cnts[4];
    #pragma unroll
    for (int jj = 0; jj < 4; jj++)
        cnts[jj] = __ldg(g_count + node0 + hw * 4 + jj);

    #pragma unroll 1
    for (int jj = 0; jj < 4; jj++) {
        int row = hw * 4 + jj;
        int n = node0 + row;
        int cnt = cnts[jj];
        const int4* ep4 = reinterpret_cast<const int4*>(g_edge + (size_t)n * CAP);

        float4 a1 = make_float4(0.f, 0.f, 0.f, 0.f);
        int e = 0;
        // 4-edge batches: two int4 record loads + 4 gathers in flight
        for (; e + 4 <= cnt; e += 4) {
            int4 ra = __ldg(ep4 + (e >> 1));
            int4 rb = __ldg(ep4 + (e >> 1) + 1);
            float4 v0 = __ldg(x4 + ra.x * 16 + le);
            float4 v1 = __ldg(x4 + ra.z * 16 + le);
            float4 v2 = __ldg(x4 + rb.x * 16 + le);
            float4 v3 = __ldg(x4 + rb.z * 16 + le);
            edge_fma(v0, __int_as_float(ra.y), a1);
            edge_fma(v1, __int_as_float(ra.w), a1);
            edge_fma(v2, __int_as_float(rb.y), a1);
            edge_fma(v3, __int_as_float(rb.w), a1);
        }
        // 2-edge batch (one int4)
        if (e + 2 <= cnt) {
            int4 ra = __ldg(ep4 + (e >> 1));
            float4 v0 = __ldg(x4 + ra.x * 16 + le);
            float4 v1 = __ldg(x4 + ra.z * 16 + le);
            edge_fma(v0, __int_as_float(ra.y), a1);
            edge_fma(v1, __int_as_float(ra.w), a1);
            e += 2;
        }
        // final single
        if (e < cnt) {
            int2 r = __ldg(reinterpret_cast<const int2*>(ep4) + e);
            float4 v0 = __ldg(x4 + r.x * 16 + le);
            edge_fma(v0, __int_as_float(r.y), a1);
        }

        float nv = __ldg(norm + n);
        float4 vd = __ldg(x4 + n * 16 + le);
        float4 f1 = make_float4(a1.x * nv, a1.y * nv, a1.z * nv, a1.w * nv);
        float4 f2 = make_float4(f1.x * vd.x, f1.y * vd.y,
                                f1.z * vd.z, f1.w * vd.w);
        *reinterpret_cast<float4*>(&f1s[row * FPAD + 4 * le]) = f1;
        *reinterpret_cast<float4*>(&f2s[row * FPAD + 4 * le]) = f2;
    }
    __syncthreads();

    // ---- Phase C: 3xBF16 m16n8k16 warp MMA ----
    int g = lane >> 2, tig = lane & 3;

    float4 acc[2][2];
    #pragma unroll
    for (int mt = 0; mt < 2; mt++)
        #pragma unroll
        for (int nt = 0; nt < 2; nt++)
            acc[mt][nt] = make_float4(0.f, 0.f, 0.f, 0.f);

    #pragma unroll
    for (int part = 0; part < 2; part++) {
        const float* fs = part ? f2s : f1s;
        #pragma unroll
        for (int ks = 0; ks < 4; ks++) {
            uint2 bh[2], bl[2];
            #pragma unroll
            for (int nt = 0; nt < 2; nt++) {
                bh[nt] = __ldg(&g_Wh[part][ks][w * 2 + nt][lane]);
                bl[nt] = __ldg(&g_Wl[part][ks][w * 2 + nt][lane]);
            }
            #pragma unroll
            for (int mt = 0; mt < 2; mt++) {
                int r0 = mt * 16 + g;
                int c0 = ks * 16 + 2 * tig;
                float2 p0 = *reinterpret_cast<const float2*>(&fs[r0 * FPAD + c0]);
                float2 p1 = *reinterpret_cast<const float2*>(&fs[(r0 + 8) * FPAD + c0]);
                float2 p2 = *reinterpret_cast<const float2*>(&fs[r0 * FPAD + c0 + 8]);
                float2 p3 = *reinterpret_cast<const float2*>(&fs[(r0 + 8) * FPAD + c0 + 8]);
                uint32_t ah0, al0, ah1, al1, ah2, al2, ah3, al3;
                split_bf2(p0, ah0, al0);
                split_bf2(p1, ah1, al1);
                split_bf2(p2, ah2, al2);
                split_bf2(p3, ah3, al3);
                #pragma unroll
                for (int nt = 0; nt < 2; nt++) {
                    mma_bf16(acc[mt][nt], ah0, ah1, ah2, ah3, bh[nt].x, bh[nt].y);
                    mma_bf16(acc[mt][nt], ah0, ah1, ah2, ah3, bl[nt].x, bl[nt].y);
                    mma_bf16(acc[mt][nt], al0, al1, al2, al3, bh[nt].x, bh[nt].y);
                }
            }
        }
    }

    // ---- epilogue ----
    #pragma unroll
    for (int nt = 0; nt < 2; nt++) {
        int colb = w * 16 + nt * 8 + 2 * tig;
        float bx = __ldg(b1v + colb)     + __ldg(b2v + colb);
        float by = __ldg(b1v + colb + 1) + __ldg(b2v + colb + 1);
        #pragma unroll
        for (int mt = 0; mt < 2; mt++) {
            int row0 = node0 + mt * 16 + g;
            float2 lo = make_float2(acc[mt][nt].x + bx, acc[mt][nt].y + by);
            float2 hi = make_float2(acc[mt][nt].z + bx, acc[mt][nt].w + by);
            *reinterpret_cast<float2*>(&out[row0 * D + colb]) = lo;
            *reinterpret_cast<float2*>(&out[(row0 + 8) * D + colb]) = hi;
        }
    }
}

// ---------------------------------------------------------------------------
// Launch
// ---------------------------------------------------------------------------
extern "C" void kernel_launch(void* const* d_in, const int* in_sizes, int n_in,
                              void* d_out, int out_size)
{
    const float* x    = (const float*)d_in[0];
    const float* norm = (const float*)d_in[1];
    const int*   src  = (const int*)  d_in[2];
    const int*   dst  = (const int*)  d_in[3];
    const float* W1   = (const float*)d_in[4];
    const float* b1   = (const float*)d_in[5];
    const float* W2   = (const float*)d_in[6];
    const float* b2   = (const float*)d_in[7];
    float* out = (float*)d_out;

    void* count_ptr;
    cudaGetSymbolAddress(&count_ptr, g_count);
    cudaMemsetAsync(count_ptr, 0, sizeof(int) * N_NODES);

    build_kernel<<<EBLOCKS + 8, 256>>>(
        reinterpret_cast<const int2*>(src),
        reinterpret_cast<const int2*>(dst), norm, W1, W2);

    size_t shmem = sizeof(float) * (2 * GEMM_NODES * FPAD);
    cudaFuncSetAttribute(fused_kernel,
                         cudaFuncAttributeMaxDynamicSharedMemorySize,
                         (int)shmem);
    fused_kernel<<<N_NODES / GEMM_NODES, 128, shmem>>>(x, norm, b1, b2, out);
}